// round 13
// baseline (speedup 1.0000x reference)
#include <cuda_runtime.h>
#include <cuda_bf16.h>

// Seq2Seq stacked GRU (L=64, H=64, D=128, B=128, T=256), wavefront-pipelined.
//  K1: precompute layer-0 input projections gi0 = x @ Wih0^T + bih0 (enc+dec)
//  K2: persistent wavefront kernel: 128 CTAs = 64 layers x 2 batch halves,
//      512 threads, j-split warp tiling. R12->R13: x/h operands stored
//      DUPLICATED in SMEM so fma.rn.f32x2 needs no pack2 broadcast MOVs;
//      ring ships dup'd pairs; h_old lives in registers.
//  K3: output projection out = dec_top @ Wo^T + bo.

#define Hn    64
#define Ln    64
#define Dn    128
#define Bn    128
#define Tn    256
#define G3H   192
#define RINGN 4          // ring depth (power of two)
#define WSTR  194        // padded SMEM stride for transposed weights (even)
#define HB    64         // batch rows per CTA (half of B)
#define WTH   512        // wave kernel threads
#define XDSTR 66         // u64-pair stride for dup'd x/h rows (16B-aligned, pad)

typedef unsigned long long u64;

// Static device scratch (allocation-free rule: __device__ globals only)
__device__ float g_gi0[2][Tn][Bn][G3H];
__device__ u64   g_xbuf[Ln][2][RINGN][HB][XDSTR];   // dup'd pairs
__device__ float g_dectop[Tn][Bn][Hn];
__device__ int   g_prog[Ln * 2];

__device__ __forceinline__ float sigf(float x) {
    return __fdividef(1.0f, 1.0f + __expf(-x));
}
__device__ __forceinline__ float tanhf_fast(float x) {
    return __fdividef(2.0f, 1.0f + __expf(-2.0f * x)) - 1.0f;
}

// ---- packed f32x2 helpers ------------------------------------------------
__device__ __forceinline__ u64 pack2(float x) {
    u64 r;
    asm("mov.b64 %0, {%1, %1};" : "=l"(r) : "f"(x));
    return r;
}
__device__ __forceinline__ void fma2(u64& d, u64 a, u64 b) {
    asm("fma.rn.f32x2 %0, %1, %2, %0;" : "+l"(d) : "l"(a), "l"(b));
}
__device__ __forceinline__ float2 unpack2(u64 v) {
    float2 r;
    asm("mov.b64 {%0, %1}, %2;" : "=f"(r.x), "=f"(r.y) : "l"(v));
    return r;
}
__device__ __forceinline__ u64 ld2(const float* p) {
    return *(const u64*)p;
}

// ---- scoped acquire/release flag ops ------------------------------------
__device__ __forceinline__ int ld_acq(const int* p) {
    int v;
    asm volatile("ld.acquire.gpu.b32 %0, [%1];" : "=r"(v) : "l"(p) : "memory");
    return v;
}
__device__ __forceinline__ void st_rel(int* p, int v) {
    asm volatile("st.release.gpu.b32 [%0], %1;" :: "l"(p), "r"(v) : "memory");
}
__device__ __forceinline__ void spin_ge(const int* p, int tgt) {
    while (ld_acq(p) < tgt) __nanosleep(64);
}

// ---------------------------------------------------------------------------
// Kernel 1: gi0 for layer 0 of both GRUs. grid = (T, 2 halves, 2 models).
// ---------------------------------------------------------------------------
#define GI0_SMEM ((Dn * WSTR + HB * Dn) * 4)

__global__ void __launch_bounds__(256, 1) gi0_kernel(
    const float* __restrict__ ctx,
    const float* __restrict__ encW0, const float* __restrict__ decW0,
    const float* __restrict__ encB,  const float* __restrict__ decB)
{
    extern __shared__ float sm[];
    float* W_s = sm;                 // [Dn][WSTR] transposed
    float* x_s = W_s + Dn * WSTR;    // [HB][Dn]

    const int t = blockIdx.x, half = blockIdx.y, m = blockIdx.z;
    const float* W0 = m ? decW0 : encW0;
    const float* bi = m ? decB  : encB;
    const int tid = threadIdx.x;
    const int warp = tid >> 5, lane = tid & 31;
    const int bb = warp * 8, jj = lane * 2;

    for (int idx = tid; idx < G3H * Dn; idx += 256) {
        int j = idx >> 7, k = idx & 127;
        W_s[k * WSTR + j] = W0[idx];
    }
    const int tt = m ? (t - 1) : t;
    if (m && t == 0) {
        for (int idx = tid; idx < HB * Dn; idx += 256) x_s[idx] = 0.f;
    } else {
        for (int idx = tid; idx < HB * Dn; idx += 256) {
            int b = idx >> 7, k = idx & 127;
            x_s[idx] = ctx[((size_t)(half * HB + b) * Tn + tt) * Dn + k];
        }
    }
    __syncthreads();

    u64 ar[8], az[8], an[8];
#pragma unroll
    for (int i = 0; i < 8; i++) { ar[i] = 0ull; az[i] = 0ull; an[i] = 0ull; }

    for (int k0 = 0; k0 < Dn; k0 += 4) {
        u64 wr[4], wz[4], wn[4];
#pragma unroll
        for (int kk = 0; kk < 4; kk++) {
            const float* wrow = &W_s[(k0 + kk) * WSTR];
            wr[kk] = ld2(&wrow[jj]);
            wz[kk] = ld2(&wrow[64 + jj]);
            wn[kk] = ld2(&wrow[128 + jj]);
        }
#pragma unroll
        for (int i = 0; i < 8; i++) {
            float4 xv = *(const float4*)&x_s[(bb + i) * Dn + k0];
            u64 xp[4] = {pack2(xv.x), pack2(xv.y), pack2(xv.z), pack2(xv.w)};
#pragma unroll
            for (int kk = 0; kk < 4; kk++) {
                fma2(ar[i], xp[kk], wr[kk]);
                fma2(az[i], xp[kk], wz[kk]);
                fma2(an[i], xp[kk], wn[kk]);
            }
        }
    }
    float2 br = *(const float2*)&bi[jj];
    float2 bz = *(const float2*)&bi[64 + jj];
    float2 bn = *(const float2*)&bi[128 + jj];
#pragma unroll
    for (int i = 0; i < 8; i++) {
        int bg = half * HB + bb + i;
        float* dst = &g_gi0[m][t][bg][0];
        float2 vr = unpack2(ar[i]), vz = unpack2(az[i]), vn = unpack2(an[i]);
        *(float2*)&dst[jj]       = make_float2(vr.x + br.x, vr.y + br.y);
        *(float2*)&dst[64 + jj]  = make_float2(vz.x + bz.x, vz.y + bz.y);
        *(float2*)&dst[128 + jj] = make_float2(vn.x + bn.x, vn.y + bn.y);
    }
}

// ---------------------------------------------------------------------------
// Kernel 2: persistent wavefront GRU stack (encoder then decoder).
// SMEM: Wih/Whh [64][WSTR] + dup'd x [HB][XDSTR]u64 + dup'd h [HB][XDSTR]u64
//       + biases. h_old is register-resident.
// ---------------------------------------------------------------------------
#define WAVE_SMEM ((2 * Hn * WSTR + 4 * HB * XDSTR + 4 * Hn) * 4)

__device__ __forceinline__ void stage_weights(
    float* Wih_s, float* Whh_s, float* cr_s, float* cz_s,
    float* bin_s, float* bhn_s,
    const float* __restrict__ Wih, const float* __restrict__ Whh,
    const float* __restrict__ bih, const float* __restrict__ bhh,
    int layer, bool isL0, int tid)
{
    if (!isL0) {
        const float* src = Wih + (size_t)(layer - 1) * G3H * Hn;
        for (int idx = tid; idx < G3H * Hn; idx += WTH) {
            int j = idx >> 6, k = idx & 63;
            Wih_s[k * WSTR + j] = src[idx];
        }
    }
    const float* srch = Whh + (size_t)layer * G3H * Hn;
    for (int idx = tid; idx < G3H * Hn; idx += WTH) {
        int j = idx >> 6, k = idx & 63;
        Whh_s[k * WSTR + j] = srch[idx];
    }
    if (tid < Hn) {
        int hj = tid;
        const float* bi = bih + layer * G3H;
        const float* bh = bhh + layer * G3H;
        cr_s[hj]  = (isL0 ? 0.f : bi[hj])      + bh[hj];
        cz_s[hj]  = (isL0 ? 0.f : bi[64 + hj]) + bh[64 + hj];
        bin_s[hj] = (isL0 ? 0.f : bi[128 + hj]);
        bhn_s[hj] = bh[128 + hj];
    }
}

__global__ void __launch_bounds__(WTH, 1) gru_wave(
    const float* __restrict__ encWih, const float* __restrict__ encWhh,
    const float* __restrict__ encBih, const float* __restrict__ encBhh,
    const float* __restrict__ decWih, const float* __restrict__ decWhh,
    const float* __restrict__ decBih, const float* __restrict__ decBhh)
{
    extern __shared__ float sm[];
    float* Wih_s = sm;                        // [64][WSTR]
    float* Whh_s = Wih_s + Hn * WSTR;         // [64][WSTR]
    u64*   xd    = (u64*)(sm + 2 * Hn * WSTR);   // [HB][XDSTR] dup pairs
    u64*   hd    = xd + HB * XDSTR;              // [HB][XDSTR] dup pairs
    float* cr_s  = (float*)(hd + HB * XDSTR);
    float* cz_s  = cr_s + Hn;
    float* bin_s = cz_s + Hn;
    float* bhn_s = bin_s + Hn;

    const int tid   = threadIdx.x;
    const int cta   = blockIdx.x;
    const int layer = cta >> 1;
    const int half  = cta & 1;
    const bool isL0 = (layer == 0);
    const int warp = tid >> 5, lane = tid & 31;
    const int rg = warp >> 1;
    const int jh = warp & 1;
    const int bb = rg * 8 + (lane >> 4) * 4;
    const int jj = jh * 32 + (lane & 15) * 2;

    int base = ld_acq(&g_prog[cta]);

    for (int i = tid; i < HB * XDSTR; i += WTH) hd[i] = 0ull;   // h0 = 0
    float hold[4][2];
#pragma unroll
    for (int i = 0; i < 4; i++) { hold[i][0] = 0.f; hold[i][1] = 0.f; }

    stage_weights(Wih_s, Whh_s, cr_s, cz_s, bin_s, bhn_s,
                  encWih, encWhh, encBih, encBhh, layer, isL0, tid);
    // prologue: stage x(0) (dup'd copy) for layers > 0
    if (!isL0) {
        spin_ge(&g_prog[cta - 2], base + 1);
        const uint4* src = (const uint4*)&g_xbuf[layer - 1][half][0][0][0];
        uint4* dst = (uint4*)xd;
        for (int i = tid; i < HB * XDSTR / 2; i += WTH) dst[i] = __ldcg(&src[i]);
    }
    __syncthreads();

    for (int t = 0; t < 2 * Tn; ++t) {
        if (t == Tn) {   // encoder -> decoder: swap weights, keep h (= h_n)
            stage_weights(Wih_s, Whh_s, cr_s, cz_s, bin_s, bhn_s,
                          decWih, decWhh, decBih, decBhh, layer, isL0, tid);
            __syncthreads();
        }

        // ---- GEMMs (packed f32x2, dup'd operands; no pack2 in loop) ----
        u64 ar[4], az[4], an[4], ahn[4];
#pragma unroll
        for (int i = 0; i < 4; i++) {
            ar[i] = 0ull; az[i] = 0ull; an[i] = 0ull; ahn[i] = 0ull;
        }

        if (!isL0) {
#pragma unroll 2
            for (int k0 = 0; k0 < Hn; k0 += 4) {
                u64 wr[4], wz[4], wn[4], ur[4], uz[4], un[4];
#pragma unroll
                for (int kk = 0; kk < 4; kk++) {
                    const float* a = &Wih_s[(k0 + kk) * WSTR];
                    const float* b = &Whh_s[(k0 + kk) * WSTR];
                    wr[kk] = ld2(&a[jj]);
                    wz[kk] = ld2(&a[64 + jj]);
                    wn[kk] = ld2(&a[128 + jj]);
                    ur[kk] = ld2(&b[jj]);
                    uz[kk] = ld2(&b[64 + jj]);
                    un[kk] = ld2(&b[128 + jj]);
                }
#pragma unroll
                for (int i = 0; i < 4; i++) {
                    const u64* xr = &xd[(bb + i) * XDSTR + k0];
                    const u64* hr = &hd[(bb + i) * XDSTR + k0];
                    ulonglong2 xa = *(const ulonglong2*)xr;
                    ulonglong2 xb = *(const ulonglong2*)(xr + 2);
                    ulonglong2 ha = *(const ulonglong2*)hr;
                    ulonglong2 hb2 = *(const ulonglong2*)(hr + 2);
                    u64 xp[4] = {xa.x, xa.y, xb.x, xb.y};
                    u64 hp[4] = {ha.x, ha.y, hb2.x, hb2.y};
#pragma unroll
                    for (int kk = 0; kk < 4; kk++) {
                        fma2(ar[i], xp[kk], wr[kk]);
                        fma2(ar[i], hp[kk], ur[kk]);
                        fma2(az[i], xp[kk], wz[kk]);
                        fma2(az[i], hp[kk], uz[kk]);
                        fma2(an[i], xp[kk], wn[kk]);
                        fma2(ahn[i], hp[kk], un[kk]);
                    }
                }
            }
        } else {
#pragma unroll 2
            for (int k0 = 0; k0 < Hn; k0 += 4) {
                u64 ur[4], uz[4], un[4];
#pragma unroll
                for (int kk = 0; kk < 4; kk++) {
                    const float* b = &Whh_s[(k0 + kk) * WSTR];
                    ur[kk] = ld2(&b[jj]);
                    uz[kk] = ld2(&b[64 + jj]);
                    un[kk] = ld2(&b[128 + jj]);
                }
#pragma unroll
                for (int i = 0; i < 4; i++) {
                    const u64* hr = &hd[(bb + i) * XDSTR + k0];
                    ulonglong2 ha = *(const ulonglong2*)hr;
                    ulonglong2 hb2 = *(const ulonglong2*)(hr + 2);
                    u64 hp[4] = {ha.x, ha.y, hb2.x, hb2.y};
#pragma unroll
                    for (int kk = 0; kk < 4; kk++) {
                        fma2(ar[i], hp[kk], ur[kk]);
                        fma2(az[i], hp[kk], uz[kk]);
                        fma2(ahn[i], hp[kk], un[kk]);
                    }
                }
            }
        }

        // ---- epilogue into registers ----
        const bool wring = (layer < Ln - 1);
        const bool wtop  = (layer == Ln - 1) && (t >= Tn);
        float2 crv = *(const float2*)&cr_s[jj];
        float2 czv = *(const float2*)&cz_s[jj];
        float2 biv = *(const float2*)&bin_s[jj];
        float2 bhv = *(const float2*)&bhn_s[jj];

        float2 gx[4][3];
        if (isL0) {
            int m  = (t < Tn) ? 0 : 1;
            int tt = (t < Tn) ? t : t - Tn;
#pragma unroll
            for (int i = 0; i < 4; i++) {
                const float* gp = &g_gi0[m][tt][half * HB + bb + i][0];
                gx[i][0] = *(const float2*)&gp[jj];
                gx[i][1] = *(const float2*)&gp[64 + jj];
                gx[i][2] = *(const float2*)&gp[128 + jj];
            }
        }

        float hw[4][2];
#pragma unroll
        for (int i = 0; i < 4; i++) {
            float2 vr = unpack2(ar[i]);
            float2 vz = unpack2(az[i]);
            float2 vn = unpack2(an[i]);
            float2 vh = unpack2(ahn[i]);
            float arr[2] = {vr.x, vr.y}, azz[2] = {vz.x, vz.y};
            float ann[2] = {vn.x, vn.y}, ahh[2] = {vh.x, vh.y};
            float crr[2] = {crv.x, crv.y}, czz[2] = {czv.x, czv.y};
            float bii[2] = {biv.x, biv.y}, bhh2[2] = {bhv.x, bhv.y};
            float gxr[2] = {gx[i][0].x, gx[i][0].y};
            float gxz[2] = {gx[i][1].x, gx[i][1].y};
            float gxn[2] = {gx[i][2].x, gx[i][2].y};
#pragma unroll
            for (int p = 0; p < 2; p++) {
                float xr, xz, xn;
                if (isL0) { xr = gxr[p]; xz = gxz[p]; xn = gxn[p]; }
                else      { xr = 0.f; xz = 0.f; xn = ann[p]; }
                float r = sigf(arr[p] + xr + crr[p]);
                float z = sigf(azz[p] + xz + czz[p]);
                float n = tanhf_fast(xn + bii[p] + r * (ahh[p] + bhh2[p]));
                hw[i][p] = (1.0f - z) * n + z * hold[i][p];
                hold[i][p] = hw[i][p];
            }
        }
        __syncthreads();   // BAR_e: all GEMM reads of xd/hd complete

        // ---- writes: h_dup (SMEM), ring (dup'd), dectop ----
        u64* ringdst = &g_xbuf[layer][half][t & (RINGN - 1)][0][0];
#pragma unroll
        for (int i = 0; i < 4; i++) {
            ulonglong2 v;
            v.x = pack2(hw[i][0]);
            v.y = pack2(hw[i][1]);
            *(ulonglong2*)&hd[(bb + i) * XDSTR + jj] = v;
            if (wtop) {
                float* td = &g_dectop[t - Tn][half * HB + bb + i][0];
                *(float2*)&td[jj] = make_float2(hw[i][0], hw[i][1]);
            }
        }
        if (wring) {
            if (t >= RINGN)   // backpressure: downstream consumed old slot
                spin_ge(&g_prog[cta + 2], base + t - RINGN + 1);
#pragma unroll
            for (int i = 0; i < 4; i++) {
                ulonglong2 v;
                v.x = pack2(hw[i][0]);
                v.y = pack2(hw[i][1]);
                *(ulonglong2*)&ringdst[(bb + i) * XDSTR + jj] = v;
            }
        }

        // ---- stage x(t+1) (layers > 0) ----
        if (!isL0 && t + 1 < 2 * Tn) {
            spin_ge(&g_prog[cta - 2], base + t + 2);
            const uint4* src = (const uint4*)
                &g_xbuf[layer - 1][half][(t + 1) & (RINGN - 1)][0][0];
            uint4* dst = (uint4*)xd;
            for (int i = tid; i < HB * XDSTR / 2; i += WTH)
                dst[i] = __ldcg(&src[i]);
        }
        __syncthreads();   // BAR_d: h_dup + staged x visible for next GEMM
        if (tid == 0) st_rel(&g_prog[cta], base + t + 1);
    }
}

// ---------------------------------------------------------------------------
// Kernel 3: output projection  out = dec_top @ Wo^T + bo. grid = (T, 2).
// ---------------------------------------------------------------------------
#define PSTR 130
#define PROJ_SMEM ((Hn * PSTR + HB * Hn) * 4)

__global__ void __launch_bounds__(256, 1) proj_kernel(
    const float* __restrict__ Wo, const float* __restrict__ bo,
    float* __restrict__ out)
{
    extern __shared__ float sm[];
    float* W_s = sm;                 // [64][PSTR] transposed
    float* x_s = W_s + Hn * PSTR;    // [HB][Hn]

    const int t = blockIdx.x, half = blockIdx.y;
    const int tid = threadIdx.x;
    const int warp = tid >> 5, lane = tid & 31;
    const int bb = warp * 8, jj = lane * 2;

    for (int idx = tid; idx < Dn * Hn; idx += 256) {
        int d = idx >> 6, k = idx & 63;
        W_s[k * PSTR + d] = Wo[idx];
    }
    for (int idx = tid; idx < HB * Hn; idx += 256) {
        x_s[idx] = g_dectop[t][half * HB + (idx >> 6)][idx & 63];
    }
    __syncthreads();

    u64 a0[8], a1[8];
#pragma unroll
    for (int i = 0; i < 8; i++) { a0[i] = 0ull; a1[i] = 0ull; }

    for (int k0 = 0; k0 < Hn; k0 += 4) {
        u64 w0[4], w1[4];
#pragma unroll
        for (int kk = 0; kk < 4; kk++) {
            const float* wrow = &W_s[(k0 + kk) * PSTR];
            w0[kk] = ld2(&wrow[jj]);
            w1[kk] = ld2(&wrow[64 + jj]);
        }
#pragma unroll
        for (int i = 0; i < 8; i++) {
            float4 xv = *(const float4*)&x_s[(bb + i) * Hn + k0];
            u64 xp[4] = {pack2(xv.x), pack2(xv.y), pack2(xv.z), pack2(xv.w)};
#pragma unroll
            for (int kk = 0; kk < 4; kk++) {
                fma2(a0[i], xp[kk], w0[kk]);
                fma2(a1[i], xp[kk], w1[kk]);
            }
        }
    }
    float2 b0 = *(const float2*)&bo[jj];
    float2 b1 = *(const float2*)&bo[64 + jj];
#pragma unroll
    for (int i = 0; i < 8; i++) {
        int bg = half * HB + bb + i;
        float* o = &out[((size_t)bg * Tn + t) * Dn];
        float2 v0 = unpack2(a0[i]), v1 = unpack2(a1[i]);
        *(float2*)&o[jj]      = make_float2(v0.x + b0.x, v0.y + b0.y);
        *(float2*)&o[64 + jj] = make_float2(v1.x + b1.x, v1.y + b1.y);
    }
}

// ---------------------------------------------------------------------------
extern "C" void kernel_launch(void* const* d_in, const int* in_sizes, int n_in,
                              void* d_out, int out_size) {
    const float* ctx     = (const float*)d_in[0];
    const float* encW0   = (const float*)d_in[1];
    const float* encWih  = (const float*)d_in[2];
    const float* encWhh  = (const float*)d_in[3];
    const float* encBih  = (const float*)d_in[4];
    const float* encBhh  = (const float*)d_in[5];
    const float* decW0   = (const float*)d_in[6];
    const float* decWih  = (const float*)d_in[7];
    const float* decWhh  = (const float*)d_in[8];
    const float* decBih  = (const float*)d_in[9];
    const float* decBhh  = (const float*)d_in[10];
    const float* Wo      = (const float*)d_in[11];
    const float* bo      = (const float*)d_in[12];
    float* out = (float*)d_out;

    cudaFuncSetAttribute(gi0_kernel,
        cudaFuncAttributeMaxDynamicSharedMemorySize, GI0_SMEM);
    cudaFuncSetAttribute(gru_wave,
        cudaFuncAttributeMaxDynamicSharedMemorySize, WAVE_SMEM);
    cudaFuncSetAttribute(proj_kernel,
        cudaFuncAttributeMaxDynamicSharedMemorySize, PROJ_SMEM);

    gi0_kernel<<<dim3(Tn, 2, 2), 256, GI0_SMEM>>>(ctx, encW0, decW0,
                                                  encBih, decBih);
    gru_wave<<<Ln * 2, WTH, WAVE_SMEM>>>(encWih, encWhh, encBih, encBhh,
                                         decWih, decWhh, decBih, decBhh);
    proj_kernel<<<dim3(Tn, 2), 256, PROJ_SMEM>>>(Wo, bo, out);
}

// round 14
// speedup vs baseline: 1.2799x; 1.2799x over previous
#include <cuda_runtime.h>
#include <cuda_bf16.h>

// Seq2Seq stacked GRU (L=64, H=64, D=128, B=128, T=256), wavefront-pipelined.
//  K1: precompute layer-0 input projections gi0 = x @ Wih0^T + bih0 (enc+dec)
//  K2: persistent wavefront kernel: 128 CTAs = 64 layers x 2 batch halves,
//      256 threads (8 warps = 4 row-tiles x 2 j-halves).
//      R14: per-step GEMM on mma.sync.m16n8k16 bf16 (HMMA tensor pipe) with
//      hi/lo bf16 3-term split for ~fp32 accuracy. Gate blocks r,z (K=128),
//      inn (x half), hn (h half) masked by k-chunk range. A=[x|h] bf16 hi/lo
//      in SMEM; weights bf16 hi/lo in SMEM; fragments via ldmatrix.
//  K3: output projection out = dec_top @ Wo^T + bo.

#define Hn    64
#define Ln    64
#define Dn    128
#define Bn    128
#define Tn    256
#define G3H   192
#define RINGN 4
#define WSTR  194        // fp32 stride (gi0 / proj kernels)
#define HB    64         // batch rows per CTA

typedef unsigned long long u64;
typedef unsigned int u32;

// Static device scratch (allocation-free rule: __device__ globals only)
__device__ float g_gi0[2][Tn][Bn][G3H];
__device__ u32   g_ring[Ln][2][RINGN][HB][64];   // [0..31]=hi bf16x2, [32..63]=lo
__device__ float g_dectop[Tn][Bn][Hn];
__device__ int   g_prog[Ln * 2];

__device__ __forceinline__ float sigf(float x) {
    return __fdividef(1.0f, 1.0f + __expf(-x));
}
__device__ __forceinline__ float tanhf_fast(float x) {
    return __fdividef(2.0f, 1.0f + __expf(-2.0f * x)) - 1.0f;
}

// ---- packed f32x2 helpers (gi0 / proj kernels) ---------------------------
__device__ __forceinline__ u64 pack2(float x) {
    u64 r; asm("mov.b64 %0, {%1, %1};" : "=l"(r) : "f"(x)); return r;
}
__device__ __forceinline__ void fma2(u64& d, u64 a, u64 b) {
    asm("fma.rn.f32x2 %0, %1, %2, %0;" : "+l"(d) : "l"(a), "l"(b));
}
__device__ __forceinline__ float2 unpack2(u64 v) {
    float2 r; asm("mov.b64 {%0, %1}, %2;" : "=f"(r.x), "=f"(r.y) : "l"(v)); return r;
}
__device__ __forceinline__ u64 ld2(const float* p) { return *(const u64*)p; }

// ---- scoped acquire/release flag ops ------------------------------------
__device__ __forceinline__ int ld_acq(const int* p) {
    int v; asm volatile("ld.acquire.gpu.b32 %0, [%1];" : "=r"(v) : "l"(p) : "memory");
    return v;
}
__device__ __forceinline__ void st_rel(int* p, int v) {
    asm volatile("st.release.gpu.b32 [%0], %1;" :: "l"(p), "r"(v) : "memory");
}
__device__ __forceinline__ void spin_ge(const int* p, int tgt) {
    while (ld_acq(p) < tgt) __nanosleep(64);
}

// ---- tensor-core helpers -------------------------------------------------
__device__ __forceinline__ unsigned smem_u32p(const void* p) {
    unsigned a;
    asm("{ .reg .u64 t; cvta.to.shared.u64 t, %1; cvt.u32.u64 %0, t; }"
        : "=r"(a) : "l"(p));
    return a;
}
__device__ __forceinline__ void ldsm4(u32* r, unsigned addr) {
    asm volatile("ldmatrix.sync.aligned.m8n8.x4.shared.b16 {%0,%1,%2,%3}, [%4];"
                 : "=r"(r[0]), "=r"(r[1]), "=r"(r[2]), "=r"(r[3]) : "r"(addr));
}
__device__ __forceinline__ void mma16816(float* c, const u32* a, u32 b0, u32 b1) {
    asm volatile(
        "mma.sync.aligned.m16n8k16.row.col.f32.bf16.bf16.f32 "
        "{%0,%1,%2,%3}, {%4,%5,%6,%7}, {%8,%9}, {%0,%1,%2,%3};"
        : "+f"(c[0]), "+f"(c[1]), "+f"(c[2]), "+f"(c[3])
        : "r"(a[0]), "r"(a[1]), "r"(a[2]), "r"(a[3]), "r"(b0), "r"(b1));
}
__device__ __forceinline__ u32 pkbf(__nv_bfloat16 a, __nv_bfloat16 b) {
    __nv_bfloat162 v = __halves2bfloat162(a, b);
    return *(u32*)&v;
}

// (g, ntp) block: load hi/lo B frags for two n-tiles, do 6 mma (3-term split)
__device__ __forceinline__ void gate_mma(
    float (*acc2)[4],            // acc[nt pair base]: two [4] accum sets
    const u32* ah, const u32* al,
    unsigned whaddr, unsigned wladdr)
{
    u32 bh[4], bl[4];
    ldsm4(bh, whaddr);
    ldsm4(bl, wladdr);
    mma16816(acc2[0], ah, bh[0], bh[1]);
    mma16816(acc2[1], ah, bh[2], bh[3]);
    mma16816(acc2[0], ah, bl[0], bl[1]);
    mma16816(acc2[1], ah, bl[2], bl[3]);
    mma16816(acc2[0], al, bh[0], bh[1]);
    mma16816(acc2[1], al, bh[2], bh[3]);
}

// ---------------------------------------------------------------------------
// Kernel 1: gi0 for layer 0 of both GRUs. grid = (T, 2 halves, 2 models).
// ---------------------------------------------------------------------------
#define GI0_SMEM ((Dn * WSTR + HB * Dn) * 4)

__global__ void __launch_bounds__(256, 1) gi0_kernel(
    const float* __restrict__ ctx,
    const float* __restrict__ encW0, const float* __restrict__ decW0,
    const float* __restrict__ encB,  const float* __restrict__ decB)
{
    extern __shared__ float sm[];
    float* W_s = sm;
    float* x_s = W_s + Dn * WSTR;

    const int t = blockIdx.x, half = blockIdx.y, m = blockIdx.z;
    const float* W0 = m ? decW0 : encW0;
    const float* bi = m ? decB  : encB;
    const int tid = threadIdx.x;
    const int warp = tid >> 5, lane = tid & 31;
    const int bb = warp * 8, jj = lane * 2;

    for (int idx = tid; idx < G3H * Dn; idx += 256) {
        int j = idx >> 7, k = idx & 127;
        W_s[k * WSTR + j] = W0[idx];
    }
    const int tt = m ? (t - 1) : t;
    if (m && t == 0) {
        for (int idx = tid; idx < HB * Dn; idx += 256) x_s[idx] = 0.f;
    } else {
        for (int idx = tid; idx < HB * Dn; idx += 256) {
            int b = idx >> 7, k = idx & 127;
            x_s[idx] = ctx[((size_t)(half * HB + b) * Tn + tt) * Dn + k];
        }
    }
    __syncthreads();

    u64 ar[8], az[8], an[8];
#pragma unroll
    for (int i = 0; i < 8; i++) { ar[i] = 0ull; az[i] = 0ull; an[i] = 0ull; }

    for (int k0 = 0; k0 < Dn; k0 += 4) {
        u64 wr[4], wz[4], wn[4];
#pragma unroll
        for (int kk = 0; kk < 4; kk++) {
            const float* wrow = &W_s[(k0 + kk) * WSTR];
            wr[kk] = ld2(&wrow[jj]);
            wz[kk] = ld2(&wrow[64 + jj]);
            wn[kk] = ld2(&wrow[128 + jj]);
        }
#pragma unroll
        for (int i = 0; i < 8; i++) {
            float4 xv = *(const float4*)&x_s[(bb + i) * Dn + k0];
            u64 xp[4] = {pack2(xv.x), pack2(xv.y), pack2(xv.z), pack2(xv.w)};
#pragma unroll
            for (int kk = 0; kk < 4; kk++) {
                fma2(ar[i], xp[kk], wr[kk]);
                fma2(az[i], xp[kk], wz[kk]);
                fma2(an[i], xp[kk], wn[kk]);
            }
        }
    }
    float2 br = *(const float2*)&bi[jj];
    float2 bz = *(const float2*)&bi[64 + jj];
    float2 bn = *(const float2*)&bi[128 + jj];
#pragma unroll
    for (int i = 0; i < 8; i++) {
        int bg = half * HB + bb + i;
        float* dst = &g_gi0[m][t][bg][0];
        float2 vr = unpack2(ar[i]), vz = unpack2(az[i]), vn = unpack2(an[i]);
        *(float2*)&dst[jj]       = make_float2(vr.x + br.x, vr.y + br.y);
        *(float2*)&dst[64 + jj]  = make_float2(vz.x + bz.x, vz.y + bz.y);
        *(float2*)&dst[128 + jj] = make_float2(vn.x + bn.x, vn.y + bn.y);
    }
}

// ---------------------------------------------------------------------------
// Kernel 2: tensor-core wavefront. 128 CTAs x 256 threads.
// SMEM layout (bytes), all bf16 tiles use 272-byte row stride (136 bf16):
//   WH [256 j'][136]  @ 0        (69,632)   j' = gate*64 + j; k: 0-63 x, 64-127 h
//   WL [256 j'][136]  @ 69632    (69,632)
//   AH [64 row][136]  @ 139264   (17,408)   k: 0-63 x, 64-127 h
//   AL [64 row][136]  @ 156672   (17,408)
//   biases (4 x 64 f32) @ 174080 (1,024)
// ---------------------------------------------------------------------------
#define WH_OFF   0
#define WL_OFF   69632
#define AH_OFF   139264
#define AL_OFF   156672
#define BIAS_OFF 174080
#define WAVE_SMEM 175104
#define BSTR 272           // bytes per bf16 tile row

__device__ void stage_w_mma(char* smem,
    const float* __restrict__ Wih, const float* __restrict__ Whh,
    const float* __restrict__ bih, const float* __restrict__ bhh,
    int layer, bool isL0, int tid)
{
    const float* wih_l = isL0 ? Wih : (Wih + (size_t)(layer - 1) * G3H * Hn);
    const float* whh_l = Whh + (size_t)layer * G3H * Hn;
    for (int idx = tid; idx < 256 * 128; idx += 256) {
        int jp = idx >> 7, k = idx & 127;
        int g = jp >> 6, j = jp & 63;
        int sr = (g >= 2 ? 128 : g * 64) + j;
        float w;
        if (k < 64) w = (isL0 || g == 3) ? 0.f : wih_l[sr * 64 + k];
        else        w = (g == 2) ? 0.f : whh_l[sr * 64 + (k - 64)];
        __nv_bfloat16 hb = __float2bfloat16_rn(w);
        __nv_bfloat16 lb = __float2bfloat16_rn(w - __bfloat162float(hb));
        *(__nv_bfloat16*)(smem + WH_OFF + jp * BSTR + k * 2) = hb;
        *(__nv_bfloat16*)(smem + WL_OFF + jp * BSTR + k * 2) = lb;
    }
    float* bias = (float*)(smem + BIAS_OFF);
    if (tid < Hn) {
        int hj = tid;
        const float* bi = bih + layer * G3H;
        const float* bh = bhh + layer * G3H;
        bias[hj]        = (isL0 ? 0.f : bi[hj])      + bh[hj];
        bias[64 + hj]   = (isL0 ? 0.f : bi[64 + hj]) + bh[64 + hj];
        bias[128 + hj]  = (isL0 ? 0.f : bi[128 + hj]);
        bias[192 + hj]  = bh[128 + hj];
    }
}

__global__ void __launch_bounds__(256, 1) gru_wave(
    const float* __restrict__ encWih, const float* __restrict__ encWhh,
    const float* __restrict__ encBih, const float* __restrict__ encBhh,
    const float* __restrict__ decWih, const float* __restrict__ decWhh,
    const float* __restrict__ decBih, const float* __restrict__ decBhh)
{
    extern __shared__ char smem[];
    const int tid   = threadIdx.x;
    const int cta   = blockIdx.x;
    const int layer = cta >> 1;
    const int half  = cta & 1;
    const bool isL0 = (layer == 0);
    const int warp = tid >> 5, lane = tid & 31;
    const int rg = warp >> 1;          // row-tile 0..3 (16 rows each)
    const int jh = warp & 1;           // j-half: 32 gate-cols
    const int r0 = rg * 16;
    const int lrow = lane >> 2;        // 0..7
    const int lcol = (lane & 3) * 2;   // 0,2,4,6
    const int g8 = lane >> 3, l7 = lane & 7;

    const unsigned sb  = smem_u32p(smem);
    const unsigned AHb = sb + AH_OFF, ALb = sb + AL_OFF;
    const unsigned WHb = sb + WH_OFF, WLb = sb + WL_OFF;
    float* bias = (float*)(smem + BIAS_OFF);

    // per-lane ldmatrix offsets
    const unsigned a_off =
        (unsigned)((r0 + ((g8 & 1) ? 8 : 0) + l7) * BSTR + ((g8 & 2) ? 16 : 0));
    const unsigned b_off =
        (unsigned)((((g8 >= 2) ? 8 : 0) + l7) * BSTR + ((g8 & 1) ? 16 : 0));

    int base = ld_acq(&g_prog[cta]);

    // h0 = 0: zero A h-region (k 64..127 -> bytes 128..255), hi and lo
    for (int i = tid; i < HB * 32; i += 256) {
        int row = i >> 5, c = i & 31;
        *(u32*)(smem + AH_OFF + row * BSTR + 128 + c * 4) = 0u;
        *(u32*)(smem + AL_OFF + row * BSTR + 128 + c * 4) = 0u;
    }
    stage_w_mma(smem, encWih, encWhh, encBih, encBhh, layer, isL0, tid);

    // prologue: stage x(0) for layers > 0
    if (!isL0) {
        spin_ge(&g_prog[cta - 2], base + 1);
        const u32* src = &g_ring[layer - 1][half][0][0][0];
        for (int i = tid; i < HB * 64; i += 256) {
            int row = i >> 6, c = i & 63;
            u32 v = __ldcg(&src[i]);
            char* dst = smem + ((c < 32) ? AH_OFF : AL_OFF);
            *(u32*)(dst + row * BSTR + (c & 31) * 4) = v;
        }
    }
    __syncthreads();

    // bias regs (reloaded at phase switch)
    float2 crv[4], czv[4], biv[4], bhv[4];
#pragma unroll
    for (int nt = 0; nt < 4; nt++) {
        int j0 = jh * 32 + nt * 8 + lcol;
        crv[nt] = *(const float2*)&bias[j0];
        czv[nt] = *(const float2*)&bias[64 + j0];
        biv[nt] = *(const float2*)&bias[128 + j0];
        bhv[nt] = *(const float2*)&bias[192 + j0];
    }

    float ho[4][4];     // h_old: [nt][q*2+p]
#pragma unroll
    for (int nt = 0; nt < 4; nt++)
#pragma unroll
        for (int c = 0; c < 4; c++) ho[nt][c] = 0.f;

    for (int t = 0; t < 2 * Tn; ++t) {
        if (t == Tn) {   // encoder -> decoder: swap weights, keep h
            __syncthreads();
            stage_w_mma(smem, decWih, decWhh, decBih, decBhh, layer, isL0, tid);
            __syncthreads();
#pragma unroll
            for (int nt = 0; nt < 4; nt++) {
                int j0 = jh * 32 + nt * 8 + lcol;
                crv[nt] = *(const float2*)&bias[j0];
                czv[nt] = *(const float2*)&bias[64 + j0];
                biv[nt] = *(const float2*)&bias[128 + j0];
                bhv[nt] = *(const float2*)&bias[192 + j0];
            }
        }

        // ---- GEMM: acc[gate][nt][4] ----
        float acc[4][4][4];
#pragma unroll
        for (int g = 0; g < 4; g++)
#pragma unroll
            for (int nt = 0; nt < 4; nt++)
#pragma unroll
                for (int c = 0; c < 4; c++) acc[g][nt][c] = 0.f;

        const unsigned jhb = (unsigned)(jh * 32) * BSTR;
        if (!isL0) {
#pragma unroll
            for (int kc = 0; kc < 8; kc++) {
                u32 ah[4], al[4];
                unsigned ao = a_off + kc * 32;
                ldsm4(ah, AHb + ao);
                ldsm4(al, ALb + ao);
#pragma unroll
                for (int ntp = 0; ntp < 2; ntp++) {
                    unsigned bo = jhb + (unsigned)(ntp * 16) * BSTR + b_off + kc * 32;
                    gate_mma(&acc[0][ntp * 2], ah, al,
                             WHb + bo, WLb + bo);                    // r
                    gate_mma(&acc[1][ntp * 2], ah, al,
                             WHb + 64u * BSTR + bo, WLb + 64u * BSTR + bo); // z
                    if (kc < 4)
                        gate_mma(&acc[2][ntp * 2], ah, al,
                                 WHb + 128u * BSTR + bo, WLb + 128u * BSTR + bo); // inn
                    else
                        gate_mma(&acc[3][ntp * 2], ah, al,
                                 WHb + 192u * BSTR + bo, WLb + 192u * BSTR + bo); // hn
                }
            }
        } else {
#pragma unroll
            for (int kc = 4; kc < 8; kc++) {
                u32 ah[4], al[4];
                unsigned ao = a_off + kc * 32;
                ldsm4(ah, AHb + ao);
                ldsm4(al, ALb + ao);
#pragma unroll
                for (int ntp = 0; ntp < 2; ntp++) {
                    unsigned bo = jhb + (unsigned)(ntp * 16) * BSTR + b_off + kc * 32;
                    gate_mma(&acc[0][ntp * 2], ah, al, WHb + bo, WLb + bo);
                    gate_mma(&acc[1][ntp * 2], ah, al,
                             WHb + 64u * BSTR + bo, WLb + 64u * BSTR + bo);
                    gate_mma(&acc[3][ntp * 2], ah, al,
                             WHb + 192u * BSTR + bo, WLb + 192u * BSTR + bo);
                }
            }
        }

        // ---- epilogue: gates + h update (registers) ----
        const bool wring = (layer < Ln - 1);
        const bool wtop  = (layer == Ln - 1) && (t >= Tn);
        const int m  = (t < Tn) ? 0 : 1;
        const int tt = (t < Tn) ? t : t - Tn;

        u32 hwh[4][2], hwl[4][2];   // [nt][q] packed bf16x2 of h (j0, j0+1)
        float hnewv[4][4];
#pragma unroll
        for (int nt = 0; nt < 4; nt++) {
            int j0 = jh * 32 + nt * 8 + lcol;
#pragma unroll
            for (int q = 0; q < 2; q++) {
                const float* gp = isL0 ?
                    &g_gi0[m][tt][half * HB + r0 + lrow + q * 8][0] : (const float*)0;
                float2 gr = isL0 ? *(const float2*)&gp[j0]       : make_float2(0.f, 0.f);
                float2 gz = isL0 ? *(const float2*)&gp[64 + j0]  : make_float2(0.f, 0.f);
                float2 gn = isL0 ? *(const float2*)&gp[128 + j0] : make_float2(0.f, 0.f);
                float grv[2] = {gr.x, gr.y}, gzv[2] = {gz.x, gz.y}, gnv[2] = {gn.x, gn.y};
                float hv2[2];
#pragma unroll
                for (int p = 0; p < 2; p++) {
                    int ci = q * 2 + p;
                    float cb[2] = {crv[nt].x, crv[nt].y};
                    float zb[2] = {czv[nt].x, czv[nt].y};
                    float ib[2] = {biv[nt].x, biv[nt].y};
                    float hb2[2] = {bhv[nt].x, bhv[nt].y};
                    float r = sigf(acc[0][nt][ci] + grv[p] + cb[p]);
                    float z = sigf(acc[1][nt][ci] + gzv[p] + zb[p]);
                    float xn = isL0 ? gnv[p] : acc[2][nt][ci];
                    float n = tanhf_fast(xn + ib[p] + r * (acc[3][nt][ci] + hb2[p]));
                    float hnew = (1.0f - z) * n + z * ho[nt][ci];
                    ho[nt][ci] = hnew;
                    hnewv[nt][ci] = hnew;
                    hv2[p] = hnew;
                }
                __nv_bfloat16 h0h = __float2bfloat16_rn(hv2[0]);
                __nv_bfloat16 h1h = __float2bfloat16_rn(hv2[1]);
                __nv_bfloat16 h0l = __float2bfloat16_rn(hv2[0] - __bfloat162float(h0h));
                __nv_bfloat16 h1l = __float2bfloat16_rn(hv2[1] - __bfloat162float(h1h));
                hwh[nt][q] = pkbf(h0h, h1h);
                hwl[nt][q] = pkbf(h0l, h1l);
            }
        }

        // ring / dectop writes (global; no SMEM hazard)
        if (wring) {
            if (t >= RINGN)
                spin_ge(&g_prog[cta + 2], base + t - RINGN + 1);
            u32* rdst = &g_ring[layer][half][t & (RINGN - 1)][0][0];
#pragma unroll
            for (int nt = 0; nt < 4; nt++) {
                int ju = (jh * 32 + nt * 8 + lcol) >> 1;
#pragma unroll
                for (int q = 0; q < 2; q++) {
                    int R = r0 + lrow + q * 8;
                    rdst[R * 64 + ju]      = hwh[nt][q];
                    rdst[R * 64 + 32 + ju] = hwl[nt][q];
                }
            }
        }
        if (wtop) {
#pragma unroll
            for (int nt = 0; nt < 4; nt++) {
                int j0 = jh * 32 + nt * 8 + lcol;
#pragma unroll
                for (int q = 0; q < 2; q++) {
                    int R = r0 + lrow + q * 8;
                    *(float2*)&g_dectop[t - Tn][half * HB + R][j0] =
                        make_float2(hnewv[nt][q * 2], hnewv[nt][q * 2 + 1]);
                }
            }
        }
        __syncthreads();   // BAR_e: all GEMM reads of A done; ring writes done
        if (tid == 0) st_rel(&g_prog[cta], base + t + 1);   // early release

        // h(t+1) into A h-region
#pragma unroll
        for (int nt = 0; nt < 4; nt++) {
            int j0 = jh * 32 + nt * 8 + lcol;
#pragma unroll
            for (int q = 0; q < 2; q++) {
                int R = r0 + lrow + q * 8;
                *(u32*)(smem + AH_OFF + R * BSTR + 128 + j0 * 2) = hwh[nt][q];
                *(u32*)(smem + AL_OFF + R * BSTR + 128 + j0 * 2) = hwl[nt][q];
            }
        }
        // stage x(t+1) into A x-region (layers > 0)
        if (!isL0 && t + 1 < 2 * Tn) {
            spin_ge(&g_prog[cta - 2], base + t + 2);
            const u32* src = &g_ring[layer - 1][half][(t + 1) & (RINGN - 1)][0][0];
            for (int i = tid; i < HB * 64; i += 256) {
                int row = i >> 6, c = i & 63;
                u32 v = __ldcg(&src[i]);
                char* dst = smem + ((c < 32) ? AH_OFF : AL_OFF);
                *(u32*)(dst + row * BSTR + (c & 31) * 4) = v;
            }
        }
        __syncthreads();   // BAR_d: A ready for next GEMM
    }
}

// ---------------------------------------------------------------------------
// Kernel 3: output projection  out = dec_top @ Wo^T + bo. grid = (T, 2).
// ---------------------------------------------------------------------------
#define PSTR 130
#define PROJ_SMEM ((Hn * PSTR + HB * Hn) * 4)

__global__ void __launch_bounds__(256, 1) proj_kernel(
    const float* __restrict__ Wo, const float* __restrict__ bo,
    float* __restrict__ out)
{
    extern __shared__ float sm[];
    float* W_s = sm;
    float* x_s = W_s + Hn * PSTR;

    const int t = blockIdx.x, half = blockIdx.y;
    const int tid = threadIdx.x;
    const int warp = tid >> 5, lane = tid & 31;
    const int bb = warp * 8, jj = lane * 2;

    for (int idx = tid; idx < Dn * Hn; idx += 256) {
        int d = idx >> 6, k = idx & 63;
        W_s[k * PSTR + d] = Wo[idx];
    }
    for (int idx = tid; idx < HB * Hn; idx += 256) {
        x_s[idx] = g_dectop[t][half * HB + (idx >> 6)][idx & 63];
    }
    __syncthreads();

    u64 a0[8], a1[8];
#pragma unroll
    for (int i = 0; i < 8; i++) { a0[i] = 0ull; a1[i] = 0ull; }

    for (int k0 = 0; k0 < Hn; k0 += 4) {
        u64 w0[4], w1[4];
#pragma unroll
        for (int kk = 0; kk < 4; kk++) {
            const float* wrow = &W_s[(k0 + kk) * PSTR];
            w0[kk] = ld2(&wrow[jj]);
            w1[kk] = ld2(&wrow[64 + jj]);
        }
#pragma unroll
        for (int i = 0; i < 8; i++) {
            float4 xv = *(const float4*)&x_s[(bb + i) * Hn + k0];
            u64 xp[4] = {pack2(xv.x), pack2(xv.y), pack2(xv.z), pack2(xv.w)};
#pragma unroll
            for (int kk = 0; kk < 4; kk++) {
                fma2(a0[i], xp[kk], w0[kk]);
                fma2(a1[i], xp[kk], w1[kk]);
            }
        }
    }
    float2 b0 = *(const float2*)&bo[jj];
    float2 b1 = *(const float2*)&bo[64 + jj];
#pragma unroll
    for (int i = 0; i < 8; i++) {
        int bg = half * HB + bb + i;
        float* o = &out[((size_t)bg * Tn + t) * Dn];
        float2 v0 = unpack2(a0[i]), v1 = unpack2(a1[i]);
        *(float2*)&o[jj]      = make_float2(v0.x + b0.x, v0.y + b0.y);
        *(float2*)&o[64 + jj] = make_float2(v1.x + b1.x, v1.y + b1.y);
    }
}

// ---------------------------------------------------------------------------
extern "C" void kernel_launch(void* const* d_in, const int* in_sizes, int n_in,
                              void* d_out, int out_size) {
    const float* ctx     = (const float*)d_in[0];
    const float* encW0   = (const float*)d_in[1];
    const float* encWih  = (const float*)d_in[2];
    const float* encWhh  = (const float*)d_in[3];
    const float* encBih  = (const float*)d_in[4];
    const float* encBhh  = (const float*)d_in[5];
    const float* decW0   = (const float*)d_in[6];
    const float* decWih  = (const float*)d_in[7];
    const float* decWhh  = (const float*)d_in[8];
    const float* decBih  = (const float*)d_in[9];
    const float* decBhh  = (const float*)d_in[10];
    const float* Wo      = (const float*)d_in[11];
    const float* bo      = (const float*)d_in[12];
    float* out = (float*)d_out;

    cudaFuncSetAttribute(gi0_kernel,
        cudaFuncAttributeMaxDynamicSharedMemorySize, GI0_SMEM);
    cudaFuncSetAttribute(gru_wave,
        cudaFuncAttributeMaxDynamicSharedMemorySize, WAVE_SMEM);
    cudaFuncSetAttribute(proj_kernel,
        cudaFuncAttributeMaxDynamicSharedMemorySize, PROJ_SMEM);

    gi0_kernel<<<dim3(Tn, 2, 2), 256, GI0_SMEM>>>(ctx, encW0, decW0,
                                                  encBih, decBih);
    gru_wave<<<Ln * 2, 256, WAVE_SMEM>>>(encWih, encWhh, encBih, encBhh,
                                         decWih, decWhh, decBih, decBhh);
    proj_kernel<<<dim3(Tn, 2), 256, PROJ_SMEM>>>(Wo, bo, out);
}

// round 15
// speedup vs baseline: 1.5004x; 1.1723x over previous
#include <cuda_runtime.h>
#include <cuda_bf16.h>
#include <cuda_fp16.h>

// Seq2Seq stacked GRU (L=64, H=64, D=128, B=128, T=256), wavefront-pipelined.
//  K1: precompute layer-0 input projections gi0 = x @ Wih0^T + bih0 (enc+dec)
//  K2: persistent wavefront kernel: 128 CTAs = 64 layers x 2 batch halves,
//      256 threads (8 warps = 4 row-tiles x 2 j-halves).
//      R15: mma.sync.m16n8k16 FP16 with 2-term weight split (W = Wh + Wl,
//      both fp16; A = [x|h] single fp16). 2/3 the MMA work of R14's bf16
//      3-term split, ~64x better per-product residual than raw bf16.
//  K3: output projection out = dec_top @ Wo^T + bo.

#define Hn    64
#define Ln    64
#define Dn    128
#define Bn    128
#define Tn    256
#define G3H   192
#define RINGN 4
#define WSTR  194        // fp32 stride (gi0 / proj kernels)
#define HB    64         // batch rows per CTA

typedef unsigned long long u64;
typedef unsigned int u32;

// Static device scratch (allocation-free rule: __device__ globals only)
__device__ float g_gi0[2][Tn][Bn][G3H];
__device__ u32   g_ring[Ln][2][RINGN][HB][32];   // fp16x2 pairs (k 0..63)
__device__ float g_dectop[Tn][Bn][Hn];
__device__ int   g_prog[Ln * 2];

__device__ __forceinline__ float sigf(float x) {
    return __fdividef(1.0f, 1.0f + __expf(-x));
}
__device__ __forceinline__ float tanhf_fast(float x) {
    return __fdividef(2.0f, 1.0f + __expf(-2.0f * x)) - 1.0f;
}

// ---- packed f32x2 helpers (gi0 / proj kernels) ---------------------------
__device__ __forceinline__ u64 pack2(float x) {
    u64 r; asm("mov.b64 %0, {%1, %1};" : "=l"(r) : "f"(x)); return r;
}
__device__ __forceinline__ void fma2(u64& d, u64 a, u64 b) {
    asm("fma.rn.f32x2 %0, %1, %2, %0;" : "+l"(d) : "l"(a), "l"(b));
}
__device__ __forceinline__ float2 unpack2(u64 v) {
    float2 r; asm("mov.b64 {%0, %1}, %2;" : "=f"(r.x), "=f"(r.y) : "l"(v)); return r;
}
__device__ __forceinline__ u64 ld2(const float* p) { return *(const u64*)p; }

// ---- scoped acquire/release flag ops ------------------------------------
__device__ __forceinline__ int ld_acq(const int* p) {
    int v; asm volatile("ld.acquire.gpu.b32 %0, [%1];" : "=r"(v) : "l"(p) : "memory");
    return v;
}
__device__ __forceinline__ void st_rel(int* p, int v) {
    asm volatile("st.release.gpu.b32 [%0], %1;" :: "l"(p), "r"(v) : "memory");
}
__device__ __forceinline__ void spin_ge(const int* p, int tgt) {
    while (ld_acq(p) < tgt) __nanosleep(64);
}

// ---- tensor-core helpers -------------------------------------------------
__device__ __forceinline__ unsigned smem_u32p(const void* p) {
    unsigned a;
    asm("{ .reg .u64 t; cvta.to.shared.u64 t, %1; cvt.u32.u64 %0, t; }"
        : "=r"(a) : "l"(p));
    return a;
}
__device__ __forceinline__ void ldsm4(u32* r, unsigned addr) {
    asm volatile("ldmatrix.sync.aligned.m8n8.x4.shared.b16 {%0,%1,%2,%3}, [%4];"
                 : "=r"(r[0]), "=r"(r[1]), "=r"(r[2]), "=r"(r[3]) : "r"(addr));
}
__device__ __forceinline__ void mma16816(float* c, const u32* a, u32 b0, u32 b1) {
    asm volatile(
        "mma.sync.aligned.m16n8k16.row.col.f32.f16.f16.f32 "
        "{%0,%1,%2,%3}, {%4,%5,%6,%7}, {%8,%9}, {%0,%1,%2,%3};"
        : "+f"(c[0]), "+f"(c[1]), "+f"(c[2]), "+f"(c[3])
        : "r"(a[0]), "r"(a[1]), "r"(a[2]), "r"(a[3]), "r"(b0), "r"(b1));
}

// (gate, nt-pair) block: B hi/lo frags for two n-tiles, 4 mma (2-term split)
__device__ __forceinline__ void gate_mma2(
    float (*acc2)[4], const u32* a, unsigned whaddr, unsigned wladdr)
{
    u32 bh[4], bl[4];
    ldsm4(bh, whaddr);
    ldsm4(bl, wladdr);
    mma16816(acc2[0], a, bh[0], bh[1]);
    mma16816(acc2[1], a, bh[2], bh[3]);
    mma16816(acc2[0], a, bl[0], bl[1]);
    mma16816(acc2[1], a, bl[2], bl[3]);
}

// ---------------------------------------------------------------------------
// Kernel 1: gi0 for layer 0 of both GRUs. grid = (T, 2 halves, 2 models).
// ---------------------------------------------------------------------------
#define GI0_SMEM ((Dn * WSTR + HB * Dn) * 4)

__global__ void __launch_bounds__(256, 1) gi0_kernel(
    const float* __restrict__ ctx,
    const float* __restrict__ encW0, const float* __restrict__ decW0,
    const float* __restrict__ encB,  const float* __restrict__ decB)
{
    extern __shared__ float sm[];
    float* W_s = sm;
    float* x_s = W_s + Dn * WSTR;

    const int t = blockIdx.x, half = blockIdx.y, m = blockIdx.z;
    const float* W0 = m ? decW0 : encW0;
    const float* bi = m ? decB  : encB;
    const int tid = threadIdx.x;
    const int warp = tid >> 5, lane = tid & 31;
    const int bb = warp * 8, jj = lane * 2;

    for (int idx = tid; idx < G3H * Dn; idx += 256) {
        int j = idx >> 7, k = idx & 127;
        W_s[k * WSTR + j] = W0[idx];
    }
    const int tt = m ? (t - 1) : t;
    if (m && t == 0) {
        for (int idx = tid; idx < HB * Dn; idx += 256) x_s[idx] = 0.f;
    } else {
        for (int idx = tid; idx < HB * Dn; idx += 256) {
            int b = idx >> 7, k = idx & 127;
            x_s[idx] = ctx[((size_t)(half * HB + b) * Tn + tt) * Dn + k];
        }
    }
    __syncthreads();

    u64 ar[8], az[8], an[8];
#pragma unroll
    for (int i = 0; i < 8; i++) { ar[i] = 0ull; az[i] = 0ull; an[i] = 0ull; }

    for (int k0 = 0; k0 < Dn; k0 += 4) {
        u64 wr[4], wz[4], wn[4];
#pragma unroll
        for (int kk = 0; kk < 4; kk++) {
            const float* wrow = &W_s[(k0 + kk) * WSTR];
            wr[kk] = ld2(&wrow[jj]);
            wz[kk] = ld2(&wrow[64 + jj]);
            wn[kk] = ld2(&wrow[128 + jj]);
        }
#pragma unroll
        for (int i = 0; i < 8; i++) {
            float4 xv = *(const float4*)&x_s[(bb + i) * Dn + k0];
            u64 xp[4] = {pack2(xv.x), pack2(xv.y), pack2(xv.z), pack2(xv.w)};
#pragma unroll
            for (int kk = 0; kk < 4; kk++) {
                fma2(ar[i], xp[kk], wr[kk]);
                fma2(az[i], xp[kk], wz[kk]);
                fma2(an[i], xp[kk], wn[kk]);
            }
        }
    }
    float2 br = *(const float2*)&bi[jj];
    float2 bz = *(const float2*)&bi[64 + jj];
    float2 bn = *(const float2*)&bi[128 + jj];
#pragma unroll
    for (int i = 0; i < 8; i++) {
        int bg = half * HB + bb + i;
        float* dst = &g_gi0[m][t][bg][0];
        float2 vr = unpack2(ar[i]), vz = unpack2(az[i]), vn = unpack2(an[i]);
        *(float2*)&dst[jj]       = make_float2(vr.x + br.x, vr.y + br.y);
        *(float2*)&dst[64 + jj]  = make_float2(vz.x + bz.x, vz.y + bz.y);
        *(float2*)&dst[128 + jj] = make_float2(vn.x + bn.x, vn.y + bn.y);
    }
}

// ---------------------------------------------------------------------------
// Kernel 2: tensor-core wavefront. 128 CTAs x 256 threads.
// SMEM (bytes), fp16 tiles, 272-byte row stride:
//   WH [256 j'][136] @ 0       (69,632)  j' = gate*64+j; k: 0-63 x, 64-127 h
//   WL [256 j'][136] @ 69632   (69,632)  fp16 residual weights
//   A  [64 row][136] @ 139264  (17,408)  single fp16 [x|h]
//   biases (4 x 64 f32) @ 156672 (1,024)
// ---------------------------------------------------------------------------
#define WH_OFF   0
#define WL_OFF   69632
#define A_OFF    139264
#define BIAS_OFF 156672
#define WAVE_SMEM 157696
#define BSTR 272           // bytes per fp16 tile row

__device__ void stage_w_mma(char* smem,
    const float* __restrict__ Wih, const float* __restrict__ Whh,
    const float* __restrict__ bih, const float* __restrict__ bhh,
    int layer, bool isL0, int tid)
{
    const float* wih_l = isL0 ? Wih : (Wih + (size_t)(layer - 1) * G3H * Hn);
    const float* whh_l = Whh + (size_t)layer * G3H * Hn;
    for (int idx = tid; idx < 256 * 128; idx += 256) {
        int jp = idx >> 7, k = idx & 127;
        int g = jp >> 6, j = jp & 63;
        int sr = (g >= 2 ? 128 : g * 64) + j;
        float w;
        if (k < 64) w = (isL0 || g == 3) ? 0.f : wih_l[sr * 64 + k];
        else        w = (g == 2) ? 0.f : whh_l[sr * 64 + (k - 64)];
        __half hb = __float2half_rn(w);
        __half lb = __float2half_rn(w - __half2float(hb));
        *(__half*)(smem + WH_OFF + jp * BSTR + k * 2) = hb;
        *(__half*)(smem + WL_OFF + jp * BSTR + k * 2) = lb;
    }
    float* bias = (float*)(smem + BIAS_OFF);
    if (tid < Hn) {
        int hj = tid;
        const float* bi = bih + layer * G3H;
        const float* bh = bhh + layer * G3H;
        bias[hj]        = (isL0 ? 0.f : bi[hj])      + bh[hj];
        bias[64 + hj]   = (isL0 ? 0.f : bi[64 + hj]) + bh[64 + hj];
        bias[128 + hj]  = (isL0 ? 0.f : bi[128 + hj]);
        bias[192 + hj]  = bh[128 + hj];
    }
}

__global__ void __launch_bounds__(256, 1) gru_wave(
    const float* __restrict__ encWih, const float* __restrict__ encWhh,
    const float* __restrict__ encBih, const float* __restrict__ encBhh,
    const float* __restrict__ decWih, const float* __restrict__ decWhh,
    const float* __restrict__ decBih, const float* __restrict__ decBhh)
{
    extern __shared__ char smem[];
    const int tid   = threadIdx.x;
    const int cta   = blockIdx.x;
    const int layer = cta >> 1;
    const int half  = cta & 1;
    const bool isL0 = (layer == 0);
    const int warp = tid >> 5, lane = tid & 31;
    const int rg = warp >> 1;          // row-tile 0..3 (16 rows each)
    const int jh = warp & 1;           // j-half: 32 gate-cols
    const int r0 = rg * 16;
    const int lrow = lane >> 2;        // 0..7
    const int lcol = (lane & 3) * 2;   // 0,2,4,6
    const int g8 = lane >> 3, l7 = lane & 7;

    const unsigned sb  = smem_u32p(smem);
    const unsigned Ab  = sb + A_OFF;
    const unsigned WHb = sb + WH_OFF, WLb = sb + WL_OFF;
    float* bias = (float*)(smem + BIAS_OFF);

    // per-lane ldmatrix offsets
    const unsigned a_off =
        (unsigned)((r0 + ((g8 & 1) ? 8 : 0) + l7) * BSTR + ((g8 & 2) ? 16 : 0));
    const unsigned b_off =
        (unsigned)((((g8 >= 2) ? 8 : 0) + l7) * BSTR + ((g8 & 1) ? 16 : 0));

    int base = ld_acq(&g_prog[cta]);

    // h0 = 0: zero A h-region (bytes 128..255 per row)
    for (int i = tid; i < HB * 32; i += 256) {
        int row = i >> 5, c = i & 31;
        *(u32*)(smem + A_OFF + row * BSTR + 128 + c * 4) = 0u;
    }
    stage_w_mma(smem, encWih, encWhh, encBih, encBhh, layer, isL0, tid);

    // prologue: stage x(0) for layers > 0
    if (!isL0) {
        spin_ge(&g_prog[cta - 2], base + 1);
        const u32* src = &g_ring[layer - 1][half][0][0][0];
        for (int i = tid; i < HB * 32; i += 256) {
            int row = i >> 5, c = i & 31;
            *(u32*)(smem + A_OFF + row * BSTR + c * 4) = __ldcg(&src[i]);
        }
    }
    __syncthreads();

    // bias regs (reloaded at phase switch)
    float2 crv[4], czv[4], biv[4], bhv[4];
#pragma unroll
    for (int nt = 0; nt < 4; nt++) {
        int j0 = jh * 32 + nt * 8 + lcol;
        crv[nt] = *(const float2*)&bias[j0];
        czv[nt] = *(const float2*)&bias[64 + j0];
        biv[nt] = *(const float2*)&bias[128 + j0];
        bhv[nt] = *(const float2*)&bias[192 + j0];
    }

    float ho[4][4];     // h_old: [nt][q*2+p]
#pragma unroll
    for (int nt = 0; nt < 4; nt++)
#pragma unroll
        for (int c = 0; c < 4; c++) ho[nt][c] = 0.f;

    for (int t = 0; t < 2 * Tn; ++t) {
        if (t == Tn) {   // encoder -> decoder: swap weights, keep h
            __syncthreads();
            stage_w_mma(smem, decWih, decWhh, decBih, decBhh, layer, isL0, tid);
            __syncthreads();
#pragma unroll
            for (int nt = 0; nt < 4; nt++) {
                int j0 = jh * 32 + nt * 8 + lcol;
                crv[nt] = *(const float2*)&bias[j0];
                czv[nt] = *(const float2*)&bias[64 + j0];
                biv[nt] = *(const float2*)&bias[128 + j0];
                bhv[nt] = *(const float2*)&bias[192 + j0];
            }
        }

        // ---- GEMM: acc[gate][nt][4] ----
        float acc[4][4][4];
#pragma unroll
        for (int g = 0; g < 4; g++)
#pragma unroll
            for (int nt = 0; nt < 4; nt++)
#pragma unroll
                for (int c = 0; c < 4; c++) acc[g][nt][c] = 0.f;

        const unsigned jhb = (unsigned)(jh * 32) * BSTR;
        if (!isL0) {
#pragma unroll
            for (int kc = 0; kc < 8; kc++) {
                u32 a[4];
                ldsm4(a, Ab + a_off + kc * 32);
#pragma unroll
                for (int ntp = 0; ntp < 2; ntp++) {
                    unsigned bo = jhb + (unsigned)(ntp * 16) * BSTR + b_off + kc * 32;
                    gate_mma2(&acc[0][ntp * 2], a, WHb + bo, WLb + bo);          // r
                    gate_mma2(&acc[1][ntp * 2], a,
                              WHb + 64u * BSTR + bo, WLb + 64u * BSTR + bo);     // z
                    if (kc < 4)
                        gate_mma2(&acc[2][ntp * 2], a,
                                  WHb + 128u * BSTR + bo, WLb + 128u * BSTR + bo); // inn
                    else
                        gate_mma2(&acc[3][ntp * 2], a,
                                  WHb + 192u * BSTR + bo, WLb + 192u * BSTR + bo); // hn
                }
            }
        } else {
#pragma unroll
            for (int kc = 4; kc < 8; kc++) {
                u32 a[4];
                ldsm4(a, Ab + a_off + kc * 32);
#pragma unroll
                for (int ntp = 0; ntp < 2; ntp++) {
                    unsigned bo = jhb + (unsigned)(ntp * 16) * BSTR + b_off + kc * 32;
                    gate_mma2(&acc[0][ntp * 2], a, WHb + bo, WLb + bo);
                    gate_mma2(&acc[1][ntp * 2], a,
                              WHb + 64u * BSTR + bo, WLb + 64u * BSTR + bo);
                    gate_mma2(&acc[3][ntp * 2], a,
                              WHb + 192u * BSTR + bo, WLb + 192u * BSTR + bo);
                }
            }
        }

        // ---- epilogue: gates + h update (registers) ----
        const bool wring = (layer < Ln - 1);
        const bool wtop  = (layer == Ln - 1) && (t >= Tn);
        const int m  = (t < Tn) ? 0 : 1;
        const int tt = (t < Tn) ? t : t - Tn;

        u32 hwp[4][2];      // [nt][q] packed fp16x2 of h (j0, j0+1)
        float hnewv[4][4];
#pragma unroll
        for (int nt = 0; nt < 4; nt++) {
            int j0 = jh * 32 + nt * 8 + lcol;
#pragma unroll
            for (int q = 0; q < 2; q++) {
                const float* gp = isL0 ?
                    &g_gi0[m][tt][half * HB + r0 + lrow + q * 8][0] : (const float*)0;
                float2 gr = isL0 ? *(const float2*)&gp[j0]       : make_float2(0.f, 0.f);
                float2 gz = isL0 ? *(const float2*)&gp[64 + j0]  : make_float2(0.f, 0.f);
                float2 gn = isL0 ? *(const float2*)&gp[128 + j0] : make_float2(0.f, 0.f);
                float grv[2] = {gr.x, gr.y}, gzv[2] = {gz.x, gz.y}, gnv[2] = {gn.x, gn.y};
                float hv2[2];
#pragma unroll
                for (int p = 0; p < 2; p++) {
                    int ci = q * 2 + p;
                    float cb[2] = {crv[nt].x, crv[nt].y};
                    float zb[2] = {czv[nt].x, czv[nt].y};
                    float ib[2] = {biv[nt].x, biv[nt].y};
                    float hb2[2] = {bhv[nt].x, bhv[nt].y};
                    float r = sigf(acc[0][nt][ci] + grv[p] + cb[p]);
                    float z = sigf(acc[1][nt][ci] + gzv[p] + zb[p]);
                    float xn = isL0 ? gnv[p] : acc[2][nt][ci];
                    float n = tanhf_fast(xn + ib[p] + r * (acc[3][nt][ci] + hb2[p]));
                    float hnew = (1.0f - z) * n + z * ho[nt][ci];
                    ho[nt][ci] = hnew;
                    hnewv[nt][ci] = hnew;
                    hv2[p] = hnew;
                }
                __half2 hp2 = __floats2half2_rn(hv2[0], hv2[1]);
                hwp[nt][q] = *(u32*)&hp2;
            }
        }

        // ring / dectop writes (global; no SMEM hazard)
        if (wring) {
            if (t >= RINGN)
                spin_ge(&g_prog[cta + 2], base + t - RINGN + 1);
            u32* rdst = &g_ring[layer][half][t & (RINGN - 1)][0][0];
#pragma unroll
            for (int nt = 0; nt < 4; nt++) {
                int ju = (jh * 32 + nt * 8 + lcol) >> 1;
#pragma unroll
                for (int q = 0; q < 2; q++) {
                    int R = r0 + lrow + q * 8;
                    rdst[R * 32 + ju] = hwp[nt][q];
                }
            }
        }
        if (wtop) {
#pragma unroll
            for (int nt = 0; nt < 4; nt++) {
                int j0 = jh * 32 + nt * 8 + lcol;
#pragma unroll
                for (int q = 0; q < 2; q++) {
                    int R = r0 + lrow + q * 8;
                    *(float2*)&g_dectop[t - Tn][half * HB + R][j0] =
                        make_float2(hnewv[nt][q * 2], hnewv[nt][q * 2 + 1]);
                }
            }
        }
        __syncthreads();   // BAR_e: all GEMM reads of A done; ring writes done
        if (tid == 0) st_rel(&g_prog[cta], base + t + 1);   // early release

        // h(t+1) into A h-region
#pragma unroll
        for (int nt = 0; nt < 4; nt++) {
            int j0 = jh * 32 + nt * 8 + lcol;
#pragma unroll
            for (int q = 0; q < 2; q++) {
                int R = r0 + lrow + q * 8;
                *(u32*)(smem + A_OFF + R * BSTR + 128 + j0 * 2) = hwp[nt][q];
            }
        }
        // stage x(t+1) into A x-region (layers > 0)
        if (!isL0 && t + 1 < 2 * Tn) {
            spin_ge(&g_prog[cta - 2], base + t + 2);
            const u32* src = &g_ring[layer - 1][half][(t + 1) & (RINGN - 1)][0][0];
            for (int i = tid; i < HB * 32; i += 256) {
                int row = i >> 5, c = i & 31;
                *(u32*)(smem + A_OFF + row * BSTR + c * 4) = __ldcg(&src[i]);
            }
        }
        __syncthreads();   // BAR_d: A ready for next GEMM
    }
}

// ---------------------------------------------------------------------------
// Kernel 3: output projection  out = dec_top @ Wo^T + bo. grid = (T, 2).
// ---------------------------------------------------------------------------
#define PSTR 130
#define PROJ_SMEM ((Hn * PSTR + HB * Hn) * 4)

__global__ void __launch_bounds__(256, 1) proj_kernel(
    const float* __restrict__ Wo, const float* __restrict__ bo,
    float* __restrict__ out)
{
    extern __shared__ float sm[];
    float* W_s = sm;
    float* x_s = W_s + Hn * PSTR;

    const int t = blockIdx.x, half = blockIdx.y;
    const int tid = threadIdx.x;
    const int warp = tid >> 5, lane = tid & 31;
    const int bb = warp * 8, jj = lane * 2;

    for (int idx = tid; idx < Dn * Hn; idx += 256) {
        int d = idx >> 6, k = idx & 63;
        W_s[k * PSTR + d] = Wo[idx];
    }
    for (int idx = tid; idx < HB * Hn; idx += 256) {
        x_s[idx] = g_dectop[t][half * HB + (idx >> 6)][idx & 63];
    }
    __syncthreads();

    u64 a0[8], a1[8];
#pragma unroll
    for (int i = 0; i < 8; i++) { a0[i] = 0ull; a1[i] = 0ull; }

    for (int k0 = 0; k0 < Hn; k0 += 4) {
        u64 w0[4], w1[4];
#pragma unroll
        for (int kk = 0; kk < 4; kk++) {
            const float* wrow = &W_s[(k0 + kk) * PSTR];
            w0[kk] = ld2(&wrow[jj]);
            w1[kk] = ld2(&wrow[64 + jj]);
        }
#pragma unroll
        for (int i = 0; i < 8; i++) {
            float4 xv = *(const float4*)&x_s[(bb + i) * Hn + k0];
            u64 xp[4] = {pack2(xv.x), pack2(xv.y), pack2(xv.z), pack2(xv.w)};
#pragma unroll
            for (int kk = 0; kk < 4; kk++) {
                fma2(a0[i], xp[kk], w0[kk]);
                fma2(a1[i], xp[kk], w1[kk]);
            }
        }
    }
    float2 b0 = *(const float2*)&bo[jj];
    float2 b1 = *(const float2*)&bo[64 + jj];
#pragma unroll
    for (int i = 0; i < 8; i++) {
        int bg = half * HB + bb + i;
        float* o = &out[((size_t)bg * Tn + t) * Dn];
        float2 v0 = unpack2(a0[i]), v1 = unpack2(a1[i]);
        *(float2*)&o[jj]      = make_float2(v0.x + b0.x, v0.y + b0.y);
        *(float2*)&o[64 + jj] = make_float2(v1.x + b1.x, v1.y + b1.y);
    }
}

// ---------------------------------------------------------------------------
extern "C" void kernel_launch(void* const* d_in, const int* in_sizes, int n_in,
                              void* d_out, int out_size) {
    const float* ctx     = (const float*)d_in[0];
    const float* encW0   = (const float*)d_in[1];
    const float* encWih  = (const float*)d_in[2];
    const float* encWhh  = (const float*)d_in[3];
    const float* encBih  = (const float*)d_in[4];
    const float* encBhh  = (const float*)d_in[5];
    const float* decW0   = (const float*)d_in[6];
    const float* decWih  = (const float*)d_in[7];
    const float* decWhh  = (const float*)d_in[8];
    const float* decBih  = (const float*)d_in[9];
    const float* decBhh  = (const float*)d_in[10];
    const float* Wo      = (const float*)d_in[11];
    const float* bo      = (const float*)d_in[12];
    float* out = (float*)d_out;

    cudaFuncSetAttribute(gi0_kernel,
        cudaFuncAttributeMaxDynamicSharedMemorySize, GI0_SMEM);
    cudaFuncSetAttribute(gru_wave,
        cudaFuncAttributeMaxDynamicSharedMemorySize, WAVE_SMEM);
    cudaFuncSetAttribute(proj_kernel,
        cudaFuncAttributeMaxDynamicSharedMemorySize, PROJ_SMEM);

    gi0_kernel<<<dim3(Tn, 2, 2), 256, GI0_SMEM>>>(ctx, encW0, decW0,
                                                  encBih, decBih);
    gru_wave<<<Ln * 2, 256, WAVE_SMEM>>>(encWih, encWhh, encBih, encBhh,
                                         decWih, decWhh, decBih, decBhh);
    proj_kernel<<<dim3(Tn, 2), 256, PROJ_SMEM>>>(Wo, bo, out);
}